// round 5
// baseline (speedup 1.0000x reference)
#include <cuda_runtime.h>
#include <math.h>

#define NT 2048
#define NH 2048
#define NI 1408
#define NE 8
#define TK 2
#define NP (NT*TK)

#define BM   128
#define BK   32
#define ASTR 36    // [m][k], %32==4 -> A-frag reads hit banks 4*grp+tig (bijective)

// gemm1: BN=64
#define BN1   64
#define BSTR1 72   // [k][n], %32==8 -> B-frag reads hit banks 8*tig+grp (bijective)
// gemm2: BN=128
#define BN2   128
#define BSTR2 136  // %32==8 -> same conflict-free pattern

// ---------------- scratch ----------------
__device__ int   g_cnt[NE];
__device__ int   g_off[NE + 1];
__device__ int   g_tok[NP];
__device__ float g_wt[NP];
__device__ float g_act[(size_t)NP * NI];

// ---------------- fused routing (one block) ----------------
__global__ __launch_bounds__(1024) void k_route(
    const int* __restrict__ idx, const float* __restrict__ w)
{
    __shared__ int scnt[NE], soff[NE], sfill[NE];
    int tid = threadIdx.x;
    if (tid < NE) { scnt[tid] = 0; sfill[tid] = 0; }
    __syncthreads();
    int my_e[4];
#pragma unroll
    for (int j = 0; j < 4; j++) {
        int i = tid + j * 1024;
        my_e[j] = idx[i];
        atomicAdd(&scnt[my_e[j]], 1);
    }
    __syncthreads();
    if (tid == 0) {
        int s = 0;
        for (int e = 0; e < NE; e++) {
            soff[e] = s;
            g_off[e] = s;
            g_cnt[e] = scnt[e];
            s += scnt[e];
        }
        g_off[NE] = s;
    }
    __syncthreads();
#pragma unroll
    for (int j = 0; j < 4; j++) {
        int i = tid + j * 1024;
        int e = my_e[j];
        int pos = soff[e] + atomicAdd(&sfill[e], 1);
        g_tok[pos] = i / TK;
        g_wt[pos]  = w[i];
    }
}

__global__ void k_zero(float* __restrict__ out) {
    int i = blockIdx.x * blockDim.x + threadIdx.x;
    ((float4*)out)[i] = make_float4(0.f, 0.f, 0.f, 0.f);
}

// ---------------- tf32 helpers ----------------
// fp32 -> tf32 round-to-nearest via integer add (HMMA truncates low 13 bits).
__device__ __forceinline__ unsigned rtf(float f) {
    return __float_as_uint(f) + 0x1000u;
}
__device__ __forceinline__ uint4 rtf4(float4 v) {
    uint4 r;
    r.x = rtf(v.x); r.y = rtf(v.y); r.z = rtf(v.z); r.w = rtf(v.w);
    return r;
}
__device__ __forceinline__ void mma8(float* c, const unsigned* a, const unsigned* b) {
    asm volatile(
        "mma.sync.aligned.m16n8k8.row.col.f32.tf32.tf32.f32 "
        "{%0,%1,%2,%3},{%4,%5,%6,%7},{%8,%9},{%0,%1,%2,%3};"
        : "+f"(c[0]), "+f"(c[1]), "+f"(c[2]), "+f"(c[3])
        : "r"(a[0]), "r"(a[1]), "r"(a[2]), "r"(a[3]), "r"(b[0]), "r"(b[1]));
}

#define A_WORDS  (2 * BM * ASTR)
#define B1_WORDS (2 * BK * BSTR1)
#define B2_WORDS (2 * BK * BSTR2)

// ---------------- GEMM1: act = silu(X Wg) * (X Wu) ----------------
// 128x64 tile, 8 warps 4mx2n, warp 32x32 dual-matrix (unchanged from R3)
__global__ __launch_bounds__(256) void k_gemm1(
    const float* __restrict__ hidden,
    const float* __restrict__ gate_w,
    const float* __restrict__ up_w)
{
    extern __shared__ unsigned sm[];
    unsigned* sA  = sm;
    unsigned* sBg = sA + A_WORDS;
    unsigned* sBu = sBg + B1_WORDS;
    int* toks = (int*)(sBu + B1_WORDS);

    int e = blockIdx.z, cnt = g_cnt[e];
    int m0 = blockIdx.y * BM;
    if (m0 >= cnt) return;
    int base = g_off[e];
    int n0 = blockIdx.x * BN1;
    int tid = threadIdx.x;

    if (tid < BM) {
        int m = m0 + tid;
        toks[tid] = (m < cnt) ? g_tok[base + m] : g_tok[base];
    }
    __syncthreads();

    const float* gp = gate_w + (size_t)e * NH * NI;
    const float* up = up_w   + (size_t)e * NH * NI;

    int a_m = tid >> 3, a_k = (tid & 7) << 2;
    int b_k = tid >> 4, b_n = (tid & 15) << 2;

    size_t arow[4];
#pragma unroll
    for (int p = 0; p < 4; p++) arow[p] = (size_t)toks[a_m + p * 32] * NH;

#pragma unroll
    for (int p = 0; p < 4; p++) {
        float4 v = *(const float4*)(hidden + arow[p] + a_k);
        *(uint4*)&sA[(size_t)(a_m + p * 32) * ASTR + a_k] = rtf4(v);
    }
#pragma unroll
    for (int p = 0; p < 2; p++) {
        int k = b_k + p * 16;
        float4 vg = *(const float4*)(gp + (size_t)k * NI + n0 + b_n);
        float4 vu = *(const float4*)(up + (size_t)k * NI + n0 + b_n);
        *(uint4*)&sBg[(size_t)k * BSTR1 + b_n] = rtf4(vg);
        *(uint4*)&sBu[(size_t)k * BSTR1 + b_n] = rtf4(vu);
    }
    __syncthreads();

    int lane = tid & 31, wid = tid >> 5;
    int wm = (wid & 3) * 32, wn = (wid >> 2) * 32;
    int grp = lane >> 2, tig = lane & 3;

    float accg[2][4][4] = {}, accu[2][4][4] = {};
    float4 pa[4], pg[2], pu[2];

    for (int k0 = 0; k0 < NH; k0 += BK) {
        int s = (k0 / BK) & 1;
        bool nxt = (k0 + BK) < NH;
        if (nxt) {
            int kn = k0 + BK;
#pragma unroll
            for (int p = 0; p < 4; p++)
                pa[p] = *(const float4*)(hidden + arow[p] + kn + a_k);
#pragma unroll
            for (int p = 0; p < 2; p++) {
                int k = b_k + p * 16;
                pg[p] = *(const float4*)(gp + (size_t)(kn + k) * NI + n0 + b_n);
                pu[p] = *(const float4*)(up + (size_t)(kn + k) * NI + n0 + b_n);
            }
        }

        const unsigned* As = sA  + (size_t)s * BM * ASTR;
        const unsigned* Bg = sBg + (size_t)s * BK * BSTR1;
        const unsigned* Bu = sBu + (size_t)s * BK * BSTR1;

#pragma unroll
        for (int kk = 0; kk < 4; kk++) {
            int k8 = kk * 8;
            unsigned a[2][4];
#pragma unroll
            for (int mi = 0; mi < 2; mi++) {
                int mb = wm + mi * 16 + grp;
                a[mi][0] = As[(mb    ) * ASTR + k8 + tig    ];
                a[mi][1] = As[(mb + 8) * ASTR + k8 + tig    ];
                a[mi][2] = As[(mb    ) * ASTR + k8 + tig + 4];
                a[mi][3] = As[(mb + 8) * ASTR + k8 + tig + 4];
            }
#pragma unroll
            for (int nj = 0; nj < 4; nj++) {
                int nb = wn + nj * 8 + grp;
                unsigned b[2];
                b[0] = Bg[(k8 + tig) * BSTR1 + nb];
                b[1] = Bg[(k8 + tig + 4) * BSTR1 + nb];
                mma8(accg[0][nj], a[0], b);
                mma8(accg[1][nj], a[1], b);
                b[0] = Bu[(k8 + tig) * BSTR1 + nb];
                b[1] = Bu[(k8 + tig + 4) * BSTR1 + nb];
                mma8(accu[0][nj], a[0], b);
                mma8(accu[1][nj], a[1], b);
            }
        }

        if (nxt) {
            int sn = s ^ 1;
            unsigned* An  = sA  + (size_t)sn * BM * ASTR;
            unsigned* Bgn = sBg + (size_t)sn * BK * BSTR1;
            unsigned* Bun = sBu + (size_t)sn * BK * BSTR1;
#pragma unroll
            for (int p = 0; p < 4; p++)
                *(uint4*)&An[(size_t)(a_m + p * 32) * ASTR + a_k] = rtf4(pa[p]);
#pragma unroll
            for (int p = 0; p < 2; p++) {
                int k = b_k + p * 16;
                *(uint4*)&Bgn[(size_t)k * BSTR1 + b_n] = rtf4(pg[p]);
                *(uint4*)&Bun[(size_t)k * BSTR1 + b_n] = rtf4(pu[p]);
            }
        }
        __syncthreads();
    }

#pragma unroll
    for (int mi = 0; mi < 2; mi++) {
#pragma unroll
        for (int nj = 0; nj < 4; nj++) {
            int mrow = wm + mi * 16 + grp;
            int ncol = n0 + wn + nj * 8 + tig * 2;
#pragma unroll
            for (int h = 0; h < 2; h++) {
                int mr = m0 + mrow + h * 8;
                if (mr < cnt) {
                    float g0 = accg[mi][nj][2*h],     u0 = accu[mi][nj][2*h];
                    float g1 = accg[mi][nj][2*h + 1], u1 = accu[mi][nj][2*h + 1];
                    float2 v;
                    v.x = (g0 / (1.f + __expf(-g0))) * u0;
                    v.y = (g1 / (1.f + __expf(-g1))) * u1;
                    *(float2*)(g_act + (size_t)(base + mr) * NI + ncol) = v;
                }
            }
        }
    }
}

// ---------------- GEMM2: out[token] += wt * (act . Wd) ----------------
// 128x128 tile, 8 warps 4mx2n, warp 32x64 single-matrix
__global__ __launch_bounds__(256) void k_gemm2(
    const float* __restrict__ down_w,
    float* __restrict__ out)
{
    extern __shared__ unsigned sm[];
    unsigned* sA = sm;
    unsigned* sB = sA + A_WORDS;
    int*   toks = (int*)(sB + B2_WORDS);
    float* wts  = (float*)(toks + BM);

    int e = blockIdx.z, cnt = g_cnt[e];
    int m0 = blockIdx.y * BM;
    if (m0 >= cnt) return;
    int base = g_off[e];
    int n0 = blockIdx.x * BN2;
    int tid = threadIdx.x;

    if (tid < BM) {
        int m = m0 + tid;
        toks[tid] = (m < cnt) ? g_tok[base + m] : 0;
        wts[tid]  = (m < cnt) ? g_wt[base + m] : 0.f;
    }
    __syncthreads();

    const float* dp = down_w + (size_t)e * NI * NH;

    int a_m = tid >> 3, a_k = (tid & 7) << 2;
    // B staging: 32 k-rows x 128 n: each thread 4 x float4 along n
    int b_k = tid >> 3, b_n = (tid & 7) << 4;

    size_t arow[4];
#pragma unroll
    for (int p = 0; p < 4; p++) {
        int m = m0 + a_m + p * 32;
        arow[p] = (size_t)(base + (m < cnt ? m : m0)) * NI;
    }

#pragma unroll
    for (int p = 0; p < 4; p++) {
        float4 v = *(const float4*)(g_act + arow[p] + a_k);
        *(uint4*)&sA[(size_t)(a_m + p * 32) * ASTR + a_k] = rtf4(v);
    }
#pragma unroll
    for (int j = 0; j < 4; j++) {
        float4 v = *(const float4*)(dp + (size_t)b_k * NH + n0 + b_n + j * 4);
        *(uint4*)&sB[(size_t)b_k * BSTR2 + b_n + j * 4] = rtf4(v);
    }
    __syncthreads();

    int lane = tid & 31, wid = tid >> 5;
    int wm = (wid & 3) * 32, wn = (wid >> 2) * 64;
    int grp = lane >> 2, tig = lane & 3;

    float acc[2][8][4] = {};
    float4 pa[4], pb[4];

    for (int k0 = 0; k0 < NI; k0 += BK) {
        int s = (k0 / BK) & 1;
        bool nxt = (k0 + BK) < NI;
        if (nxt) {
            int kn = k0 + BK;
#pragma unroll
            for (int p = 0; p < 4; p++)
                pa[p] = *(const float4*)(g_act + arow[p] + kn + a_k);
#pragma unroll
            for (int j = 0; j < 4; j++)
                pb[j] = *(const float4*)(dp + (size_t)(kn + b_k) * NH + n0 + b_n + j * 4);
        }

        const unsigned* As = sA + (size_t)s * BM * ASTR;
        const unsigned* Bs = sB + (size_t)s * BK * BSTR2;

#pragma unroll
        for (int kk = 0; kk < 4; kk++) {
            int k8 = kk * 8;
            unsigned a[2][4];
#pragma unroll
            for (int mi = 0; mi < 2; mi++) {
                int mb = wm + mi * 16 + grp;
                a[mi][0] = As[(mb    ) * ASTR + k8 + tig    ];
                a[mi][1] = As[(mb + 8) * ASTR + k8 + tig    ];
                a[mi][2] = As[(mb    ) * ASTR + k8 + tig + 4];
                a[mi][3] = As[(mb + 8) * ASTR + k8 + tig + 4];
            }
#pragma unroll
            for (int nj = 0; nj < 8; nj++) {
                int nb = wn + nj * 8 + grp;
                unsigned b[2];
                b[0] = Bs[(k8 + tig) * BSTR2 + nb];
                b[1] = Bs[(k8 + tig + 4) * BSTR2 + nb];
                mma8(acc[0][nj], a[0], b);
                mma8(acc[1][nj], a[1], b);
            }
        }

        if (nxt) {
            int sn = s ^ 1;
            unsigned* An = sA + (size_t)sn * BM * ASTR;
            unsigned* Bn = sB + (size_t)sn * BK * BSTR2;
#pragma unroll
            for (int p = 0; p < 4; p++)
                *(uint4*)&An[(size_t)(a_m + p * 32) * ASTR + a_k] = rtf4(pa[p]);
#pragma unroll
            for (int j = 0; j < 4; j++)
                *(uint4*)&Bn[(size_t)b_k * BSTR2 + b_n + j * 4] = rtf4(pb[j]);
        }
        __syncthreads();
    }

#pragma unroll
    for (int mi = 0; mi < 2; mi++) {
#pragma unroll
        for (int nj = 0; nj < 8; nj++) {
            int mloc = wm + mi * 16 + grp;
            int ncol = n0 + wn + nj * 8 + tig * 2;
#pragma unroll
            for (int h = 0; h < 2; h++) {
                int ml = mloc + h * 8;
                int mr = m0 + ml;
                if (mr < cnt) {
                    int   t = toks[ml];
                    float w = wts[ml];
                    float* dst = out + (size_t)t * NH + ncol;
                    asm volatile("red.global.add.v2.f32 [%0], {%1,%2};"
                                 :: "l"(dst), "f"(w * acc[mi][nj][2*h]),
                                    "f"(w * acc[mi][nj][2*h + 1]) : "memory");
                }
            }
        }
    }
}

// ---------------- launch ----------------
extern "C" void kernel_launch(void* const* d_in, const int* in_sizes, int n_in,
                              void* d_out, int out_size)
{
    const float* hidden = (const float*)d_in[0];
    const int*   idx    = (const int*)  d_in[1];
    const float* topw   = (const float*)d_in[2];
    const float* gate_w = (const float*)d_in[3];
    const float* up_w   = (const float*)d_in[4];
    const float* down_w = (const float*)d_in[5];
    float* out = (float*)d_out;

    int smem1 = (A_WORDS + 2 * B1_WORDS) * 4 + BM * 4;
    int smem2 = (A_WORDS + B2_WORDS) * 4 + BM * 8;
    static int configured = 0;
    if (!configured) {
        cudaFuncSetAttribute(k_gemm1, cudaFuncAttributeMaxDynamicSharedMemorySize, smem1);
        cudaFuncSetAttribute(k_gemm2, cudaFuncAttributeMaxDynamicSharedMemorySize, smem2);
        configured = 1;
    }

    k_route<<<1, 1024>>>(idx, topw);
    k_zero<<<(NT * NH / 4) / 256, 256>>>(out);

    dim3 g1(NI / BN1, NP / BM, NE);
    k_gemm1<<<g1, 256, smem1>>>(hidden, gate_w, up_w);

    dim3 g2(NH / BN2, NP / BM, NE);
    k_gemm2<<<g2, 256, smem2>>>(down_w, out);
}